// round 1
// baseline (speedup 1.0000x reference)
#include <cuda_runtime.h>

namespace {

constexpr float PI_F   = 3.14159265358979323846f;
constexpr float R_CUT  = 5.0f;
constexpr float NORM_F = 0.17677669529663687f;  // 1/sqrt(32)

__device__ __forceinline__ void red_add_v4(float* p, float a, float b, float c, float d) {
    unsigned long long gp = __cvta_generic_to_global(p);
    asm volatile("red.global.add.v4.f32 [%0], {%1, %2, %3, %4};"
                 :: "l"(gp), "f"(a), "f"(b), "f"(c), "f"(d)
                 : "memory");
}

__global__ __launch_bounds__(256)
void sph_expand_kernel(const float* __restrict__ vectors,
                       const float* __restrict__ W,     // (4, 12, 8)
                       const int*   __restrict__ cidx,  // center index
                       const int*   __restrict__ sidx,  // species index
                       float*       __restrict__ out,   // (32768, 16, 32)
                       int n_edges)
{
    __shared__ float sW[4 * 12 * 8];
    for (int i = threadIdx.x; i < 384; i += blockDim.x) sW[i] = W[i];
    __syncthreads();

    int e = blockIdx.x * blockDim.x + threadIdx.x;
    if (e >= n_edges) return;

    float vx = vectors[3 * e + 0];
    float vy = vectors[3 * e + 1];
    float vz = vectors[3 * e + 2];

    float r2  = fmaf(vx, vx, fmaf(vy, vy, vz * vz)) + 1e-12f;
    float r   = sqrtf(r2);
    float inv = 1.0f / r;
    float x = vx * inv, y = vy * inv, z = vz * inv;

    // phi_n = sin(pi/R_CUT * r * n) / r * NORM,  n = 1..12
    // Chebyshev recurrence: sin((n+1)a) = 2cos(a) sin(na) - sin((n-1)a)
    float a = (PI_F / R_CUT) * r;
    float s0, c0;
    sincosf(a, &s0, &c0);
    float t     = NORM_F * inv;
    float two_c = 2.0f * c0;
    float phi[12];
    {
        float sm1 = 0.0f, sc = s0;
        phi[0] = sc * t;
        #pragma unroll
        for (int n = 1; n < 12; n++) {
            float s1 = fmaf(two_c, sc, -sm1);
            sm1 = sc;
            sc  = s1;
            phi[n] = sc * t;
        }
    }

    // Radial projections: rad[l][n] = sum_b phi[b] * W[l][b][n]
    float4 rad[4][2];
    #pragma unroll
    for (int l = 0; l < 4; l++) {
        rad[l][0] = make_float4(0.f, 0.f, 0.f, 0.f);
        rad[l][1] = make_float4(0.f, 0.f, 0.f, 0.f);
    }
    const float4* w4 = reinterpret_cast<const float4*>(sW);
    #pragma unroll
    for (int b = 0; b < 12; b++) {
        float p = phi[b];
        #pragma unroll
        for (int l = 0; l < 4; l++) {
            float4 w0 = w4[l * 24 + b * 2 + 0];
            float4 w1 = w4[l * 24 + b * 2 + 1];
            rad[l][0].x = fmaf(p, w0.x, rad[l][0].x);
            rad[l][0].y = fmaf(p, w0.y, rad[l][0].y);
            rad[l][0].z = fmaf(p, w0.z, rad[l][0].z);
            rad[l][0].w = fmaf(p, w0.w, rad[l][0].w);
            rad[l][1].x = fmaf(p, w1.x, rad[l][1].x);
            rad[l][1].y = fmaf(p, w1.y, rad[l][1].y);
            rad[l][1].z = fmaf(p, w1.z, rad[l][1].z);
            rad[l][1].w = fmaf(p, w1.w, rad[l][1].w);
        }
    }

    // Real spherical harmonics, l <= 3 (16 values)
    float x2 = x * x, y2 = y * y, z2 = z * z;
    float sh[16];
    sh[0]  = 0.28209479177387814f;
    sh[1]  = 0.4886025119029199f * y;
    sh[2]  = 0.4886025119029199f * z;
    sh[3]  = 0.4886025119029199f * x;
    sh[4]  = 1.0925484305920792f * x * y;
    sh[5]  = 1.0925484305920792f * y * z;
    sh[6]  = 0.31539156525252005f * fmaf(3.0f, z2, -1.0f);
    sh[7]  = 1.0925484305920792f * x * z;
    sh[8]  = 0.5462742152960396f * (x2 - y2);
    sh[9]  = 0.5900435899266435f * y * fmaf(3.0f, x2, -y2);
    sh[10] = 2.890611442640554f  * x * y * z;
    sh[11] = 0.4570457994644658f * y * fmaf(5.0f, z2, -1.0f);
    sh[12] = 0.3731763325901154f * z * fmaf(5.0f, z2, -3.0f);
    sh[13] = 0.4570457994644658f * x * fmaf(5.0f, z2, -1.0f);
    sh[14] = 1.445305721320277f  * z * (x2 - y2);
    sh[15] = 0.5900435899266435f * x * (x2 - y2);

    // Scatter: out[c][k][sp*8 + n] += sh[k] * rad[l(k)][n]
    long long base = (long long)cidx[e] * 512 + (long long)sidx[e] * 8;
    float* op = out + base;

    #pragma unroll
    for (int k = 0; k < 16; k++) {
        int l = (k >= 9) ? 3 : ((k >= 4) ? 2 : ((k >= 1) ? 1 : 0));
        float sk = sh[k];
        float4 r0 = rad[l][0];
        float4 r1 = rad[l][1];
        red_add_v4(op + k * 32,     sk * r0.x, sk * r0.y, sk * r0.z, sk * r0.w);
        red_add_v4(op + k * 32 + 4, sk * r1.x, sk * r1.y, sk * r1.z, sk * r1.w);
    }
}

} // namespace

extern "C" void kernel_launch(void* const* d_in, const int* in_sizes, int n_in,
                              void* d_out, int out_size)
{
    const float* vectors = (const float*)d_in[0];
    const float* W       = (const float*)d_in[1];
    const int*   cidx    = (const int*)d_in[2];
    const int*   sidx    = (const int*)d_in[3];
    float*       out     = (float*)d_out;

    int n_edges = in_sizes[2];   // center_index element count

    // Output is poisoned to 0xAA by the harness; zero it (memset node is capturable).
    cudaMemsetAsync(d_out, 0, (size_t)out_size * sizeof(float), 0);

    int threads = 256;
    int blocks  = (n_edges + threads - 1) / threads;
    sph_expand_kernel<<<blocks, threads>>>(vectors, W, cidx, sidx, out, n_edges);
}